// round 1
// baseline (speedup 1.0000x reference)
#include <cuda_runtime.h>
#include <math.h>

// Problem constants
#define BB  4
#define TT  16
#define HH  64
#define WW  64
#define CIN 32
#define FF  64   // per-gate channels; 4*FF = 256 gate channels

// Scratch (static device memory; no allocation in kernel_launch)
__device__ float4 g_Whr[9 * 64 * 64];      // [k][ci][f] -> gates {i,f,c,o}
__device__ float4 g_Wxr[9 * 32 * 64];      // [k][ci][f] -> gates {i,f,c,o}
__device__ float4 g_br[64];                // bias per f, 4 gates
__device__ float  g_h[2][BB * HH * WW * FF];  // ping-pong hidden state, NHWC
__device__ float  g_c[BB * HH * WW * FF];     // cell state, NHWC

// ---------------------------------------------------------------------------
// Reorder weights into gate-interleaved float4 layout:
//   g_Whr[(k*64+ci)*64 + f] = { Wh[k][ci][f], Wh[k][ci][64+f], Wh[k][ci][128+f], Wh[k][ci][192+f] }
// ---------------------------------------------------------------------------
__global__ void reorder_kernel(const float* __restrict__ Wx,
                               const float* __restrict__ Wh,
                               const float* __restrict__ b)
{
    const int NH = 9 * 64 * 64;
    const int NX = 9 * 32 * 64;
    int idx = blockIdx.x * blockDim.x + threadIdx.x;
    if (idx < NH) {
        int f = idx & 63, kci = idx >> 6;
        const float* s = Wh + kci * 256 + f;
        g_Whr[idx] = make_float4(s[0], s[64], s[128], s[192]);
    } else if (idx < NH + NX) {
        int j = idx - NH;
        int f = j & 63, kci = j >> 6;
        const float* s = Wx + kci * 256 + f;
        g_Wxr[j] = make_float4(s[0], s[64], s[128], s[192]);
    } else if (idx < NH + NX + 64) {
        int f = idx - NH - NX;
        g_br[f] = make_float4(b[f], b[64 + f], b[128 + f], b[192 + f]);
    }
}

// Zero h ping buffer 0 (read at t=0) and c. Runs every launch -> graph replays
// are deterministic (step 15 writes buffer 0, re-zeroed here each replay).
__global__ void zero_kernel()
{
    int i = blockIdx.x * blockDim.x + threadIdx.x;
    if (i < BB * HH * WW * FF) { g_h[0][i] = 0.f; g_c[i] = 0.f; }
}

// ---------------------------------------------------------------------------
// One ConvLSTM timestep, fully fused:
//   z = conv3x3(x_t, Wx) + b + conv3x3(h_{t-1}, Wh)
//   i,f,o = hard_sigmoid(z.), c_t = f*c + i*tanh(zc), h_t = o*tanh(c_t)
//   out[t] = h_t + (conv1x1(x_t, Wp) + bp)
//
// Block: 8x8 spatial tile x 64 f-channels. 256 threads.
//   tid = pg*64 + f ; pg in 0..3 owns 2 rows (16 pixels), thread keeps
//   16 pixels x 4 gates = 64 fp32 accumulators.
// ---------------------------------------------------------------------------
__global__ __launch_bounds__(256, 2)
void step_kernel(const float* __restrict__ x,
                 const float* __restrict__ Wp,
                 const float* __restrict__ bp,
                 float* __restrict__ out,
                 int t)
{
    __shared__ float sh_h[10 * 10 * 64];  // 25.6 KB: h tile with halo
    __shared__ float sh_x[10 * 10 * 32];  // 12.8 KB: x tile with halo

    const int bI  = blockIdx.z;
    const int tx0 = blockIdx.x * 8;
    const int ty0 = blockIdx.y * 8;
    const int tid = threadIdx.x;
    const int f   = tid & 63;
    const int pg  = tid >> 6;
    const int pr0 = pg * 2;

    const float* __restrict__ hin  = g_h[t & 1];
    float*       __restrict__ hout = g_h[(t + 1) & 1];

    // --- load h tile (zero-padded halo) ---
    for (int s = tid; s < 10 * 10 * 64; s += 256) {
        int ci = s & 63, sp = s >> 6;
        int rx = sp % 10, ry = sp / 10;
        int gy = ty0 - 1 + ry, gx = tx0 - 1 + rx;
        float v = 0.f;
        if ((unsigned)gy < 64u && (unsigned)gx < 64u)
            v = hin[((bI * 64 + gy) * 64 + gx) * 64 + ci];
        sh_h[s] = v;
    }
    // --- load x tile (zero-padded halo) ---
    const float* __restrict__ xt = x + (size_t)(bI * TT + t) * (HH * WW * CIN);
    for (int s = tid; s < 10 * 10 * 32; s += 256) {
        int ci = s & 31, sp = s >> 5;
        int rx = sp % 10, ry = sp / 10;
        int gy = ty0 - 1 + ry, gx = tx0 - 1 + rx;
        float v = 0.f;
        if ((unsigned)gy < 64u && (unsigned)gx < 64u)
            v = xt[(gy * 64 + gx) * 32 + ci];
        sh_x[s] = v;
    }
    __syncthreads();

    // --- accumulators: 16 pixels x {i,f,c,o} ---
    float4 acc[16];
    {
        float4 bias = g_br[f];
#pragma unroll
        for (int p = 0; p < 16; ++p) acc[p] = bias;
    }

    // --- recurrent conv: h (ci=64) ---
    for (int k = 0; k < 9; ++k) {
        const int dy = k / 3, dx = k - dy * 3;
        const float4* __restrict__ wbase = g_Whr + (k * 64) * 64 + f;
        const float*  __restrict__ hbase = sh_h + ((pr0 + dy) * 10 + dx) * 64;
#pragma unroll 2
        for (int ci = 0; ci < 64; ++ci) {
            float4 w = wbase[ci * 64];
#pragma unroll
            for (int r = 0; r < 2; ++r)
#pragma unroll
                for (int cx = 0; cx < 8; ++cx) {
                    float hv = hbase[(r * 10 + cx) * 64 + ci];
                    float4& a = acc[r * 8 + cx];
                    a.x = fmaf(hv, w.x, a.x);
                    a.y = fmaf(hv, w.y, a.y);
                    a.z = fmaf(hv, w.z, a.z);
                    a.w = fmaf(hv, w.w, a.w);
                }
        }
    }

    // --- input conv: x (ci=32) ---
    for (int k = 0; k < 9; ++k) {
        const int dy = k / 3, dx = k - dy * 3;
        const float4* __restrict__ wbase = g_Wxr + (k * 32) * 64 + f;
        const float*  __restrict__ xbase = sh_x + ((pr0 + dy) * 10 + dx) * 32;
#pragma unroll 2
        for (int ci = 0; ci < 32; ++ci) {
            float4 w = wbase[ci * 64];
#pragma unroll
            for (int r = 0; r < 2; ++r)
#pragma unroll
                for (int cx = 0; cx < 8; ++cx) {
                    float xv = xbase[(r * 10 + cx) * 32 + ci];
                    float4& a = acc[r * 8 + cx];
                    a.x = fmaf(xv, w.x, a.x);
                    a.y = fmaf(xv, w.y, a.y);
                    a.z = fmaf(xv, w.z, a.z);
                    a.w = fmaf(xv, w.w, a.w);
                }
        }
    }

    // --- gates + state update ---
    float hn[16];
#pragma unroll
    for (int p = 0; p < 16; ++p) {
        int py = ty0 + pr0 + (p >> 3);
        int px = tx0 + (p & 7);
        int cidx = ((bI * 64 + py) * 64 + px) * 64 + f;
        float ig = __saturatef(fmaf(0.2f, acc[p].x, 0.5f));
        float fg = __saturatef(fmaf(0.2f, acc[p].y, 0.5f));
        float og = __saturatef(fmaf(0.2f, acc[p].w, 0.5f));
        float cn = fmaf(fg, g_c[cidx], ig * tanhf(acc[p].z));
        g_c[cidx]  = cn;
        float hv = og * tanhf(cn);
        hout[cidx] = hv;
        hn[p] = hv;
    }

    // --- residual 1x1 projection (x tile already in smem) ---
    float res[16];
    {
        float bpf = __ldg(bp + f);
#pragma unroll
        for (int p = 0; p < 16; ++p) res[p] = bpf;
    }
#pragma unroll 2
    for (int ci = 0; ci < 32; ++ci) {
        float wv = __ldg(Wp + ci * 64 + f);
#pragma unroll
        for (int r = 0; r < 2; ++r)
#pragma unroll
            for (int cx = 0; cx < 8; ++cx) {
                float xv = sh_x[((pr0 + 1 + r) * 10 + (cx + 1)) * 32 + ci];
                res[r * 8 + cx] = fmaf(xv, wv, res[r * 8 + cx]);
            }
    }

    // --- write output ---
    float* __restrict__ op = out + (size_t)(bI * TT + t) * 4096 * 64;
#pragma unroll
    for (int p = 0; p < 16; ++p) {
        int py = ty0 + pr0 + (p >> 3);
        int px = tx0 + (p & 7);
        op[(py * 64 + px) * 64 + f] = hn[p] + res[p];
    }
}

// ---------------------------------------------------------------------------
extern "C" void kernel_launch(void* const* d_in, const int* in_sizes, int n_in,
                              void* d_out, int out_size)
{
    const float* x  = (const float*)d_in[0];
    const float* Wx = (const float*)d_in[1];
    const float* Wh = (const float*)d_in[2];
    const float* b  = (const float*)d_in[3];
    const float* Wp = (const float*)d_in[4];
    const float* bp = (const float*)d_in[5];
    float* out = (float*)d_out;

    const int nre = 9 * 64 * 64 + 9 * 32 * 64 + 64;
    reorder_kernel<<<(nre + 255) / 256, 256>>>(Wx, Wh, b);

    const int nz = BB * HH * WW * FF;
    zero_kernel<<<(nz + 255) / 256, 256>>>();

    dim3 grid(8, 8, BB);
    for (int t = 0; t < TT; ++t)
        step_kernel<<<grid, 256>>>(x, Wp, bp, out, t);
}

// round 4
// speedup vs baseline: 1.3051x; 1.3051x over previous
#include <cuda_runtime.h>
#include <math.h>

typedef unsigned long long ull;

// Problem constants
#define BB  4
#define TT  16
#define HH  64
#define WW  64
#define CIN 32
#define FF  64   // per-gate channels; 4*FF = 256 gate channels

// Packed weights: per (k,ci,f): [0]=pack(w_i,w_f), [1]=pack(w_c,w_o)
__device__ ull   g_Wh2[9 * 64 * 64 * 2];   // 589KB
__device__ ull   g_Wx2[9 * 32 * 64 * 2];   // 294KB
__device__ float4 g_br[64];                // bias per f: {b_i,b_f,b_c,b_o}
__device__ float g_h[2][BB * HH * WW * FF];  // ping-pong hidden state, NHWC
__device__ float g_c[BB * HH * WW * FF];     // cell state, NHWC

__device__ __forceinline__ ull pack2(float lo, float hi) {
    ull r; asm("mov.b64 %0, {%1, %2};" : "=l"(r) : "f"(lo), "f"(hi)); return r;
}
__device__ __forceinline__ float2 unpack2(ull v) {
    float2 r; asm("mov.b64 {%0, %1}, %2;" : "=f"(r.x), "=f"(r.y) : "l"(v)); return r;
}
#define FMA2(d, a, b) asm("fma.rn.f32x2 %0, %1, %2, %0;" : "+l"(d) : "l"(a), "l"(b))

// ---------------------------------------------------------------------------
// Reorder weights into gate-pair-packed f32x2 layout.
//   g_Wh2[((k*64+ci)*64+f)*2 + 0] = pack(Wh[k][ci][0*64+f], Wh[k][ci][1*64+f])
//   g_Wh2[((k*64+ci)*64+f)*2 + 1] = pack(Wh[k][ci][2*64+f], Wh[k][ci][3*64+f])
// ---------------------------------------------------------------------------
__global__ void reorder_kernel(const float* __restrict__ Wx,
                               const float* __restrict__ Wh,
                               const float* __restrict__ b)
{
    const int NH = 9 * 64 * 64;   // (k,ci,f) triples for Wh
    const int NX = 9 * 32 * 64;
    int idx = blockIdx.x * blockDim.x + threadIdx.x;
    if (idx < NH) {
        int f = idx & 63, kci = idx >> 6;
        const float* s = Wh + kci * 256 + f;
        g_Wh2[idx * 2 + 0] = pack2(s[0],   s[64]);
        g_Wh2[idx * 2 + 1] = pack2(s[128], s[192]);
    } else if (idx < NH + NX) {
        int j = idx - NH;
        int f = j & 63, kci = j >> 6;
        const float* s = Wx + kci * 256 + f;
        g_Wx2[j * 2 + 0] = pack2(s[0],   s[64]);
        g_Wx2[j * 2 + 1] = pack2(s[128], s[192]);
    } else if (idx < NH + NX + 64) {
        int f = idx - NH - NX;
        g_br[f] = make_float4(b[f], b[64 + f], b[128 + f], b[192 + f]);
    }
}

// Zero h ping buffer 0 and c each launch -> graph replays deterministic.
__global__ void zero_kernel()
{
    int i = blockIdx.x * blockDim.x + threadIdx.x;
    if (i < BB * HH * WW * FF) { g_h[0][i] = 0.f; g_c[i] = 0.f; }
}

// ---------------------------------------------------------------------------
// One fused ConvLSTM timestep with f32x2 packed math.
// Block: 8x8 spatial tile x 64 f-channels, 256 threads.
// tid = pg*64 + f ; pg in 0..3 owns 2 rows (16 pixels).
// Accumulators: per pixel, acc_if = (z_i, z_f) and acc_co = (z_c, z_o) as f32x2.
// h/x tiles stored VALUE-DUPLICATED in smem so one LDS.128 gives two (v,v)
// f32x2 operands directly (no per-scalar MOV packing).
// ---------------------------------------------------------------------------
__global__ __launch_bounds__(256, 2)
void step_kernel(const float* __restrict__ x,
                 const float* __restrict__ Wp,
                 const float* __restrict__ bp,
                 float* __restrict__ out,
                 int t)
{
    extern __shared__ float smem[];
    float* shd_h = smem;                  // [10*10][128] duplicated: 51.2KB
    float* shd_x = smem + 100 * 128;      // [10*10][64]  duplicated: 25.6KB

    const int bI  = blockIdx.z;
    const int tx0 = blockIdx.x * 8;
    const int ty0 = blockIdx.y * 8;
    const int tid = threadIdx.x;
    const int f   = tid & 63;
    const int pg  = tid >> 6;
    const int pr0 = pg * 2;

    const float* __restrict__ hin  = g_h[t & 1];
    float*       __restrict__ hout = g_h[(t + 1) & 1];

    // --- load h tile, value-duplicated (zero-padded halo) ---
    for (int s = tid; s < 100 * 64; s += 256) {
        int ci = s & 63, sp = s >> 6;
        int rx = sp % 10, ry = sp / 10;
        int gy = ty0 - 1 + ry, gx = tx0 - 1 + rx;
        float v = 0.f;
        if ((unsigned)gy < 64u && (unsigned)gx < 64u)
            v = hin[((bI * 64 + gy) * 64 + gx) * 64 + ci];
        shd_h[sp * 128 + 2 * ci]     = v;
        shd_h[sp * 128 + 2 * ci + 1] = v;
    }
    // --- load x tile, value-duplicated ---
    const float* __restrict__ xt = x + (size_t)(bI * TT + t) * (HH * WW * CIN);
    for (int s = tid; s < 100 * 32; s += 256) {
        int ci = s & 31, sp = s >> 5;
        int rx = sp % 10, ry = sp / 10;
        int gy = ty0 - 1 + ry, gx = tx0 - 1 + rx;
        float v = 0.f;
        if ((unsigned)gy < 64u && (unsigned)gx < 64u)
            v = xt[(gy * 64 + gx) * 32 + ci];
        shd_x[sp * 64 + 2 * ci]     = v;
        shd_x[sp * 64 + 2 * ci + 1] = v;
    }
    __syncthreads();

    // --- accumulators: 16 pixels x {(i,f),(c,o)} ---
    ull acc_if[16], acc_co[16];
    {
        float4 bias = g_br[f];
        ull bif = pack2(bias.x, bias.y);
        ull bco = pack2(bias.z, bias.w);
#pragma unroll
        for (int p = 0; p < 16; ++p) { acc_if[p] = bif; acc_co[p] = bco; }
    }

    // --- recurrent conv: h (ci = 64) ---
    for (int k = 0; k < 9; ++k) {
        const int dy = k / 3, dx = k - dy * 3;
        const ull* __restrict__ wb = g_Wh2 + ((size_t)(k * 64) * 64 + f) * 2;
        const float* __restrict__ hb = shd_h + ((pr0 + dy) * 10 + dx) * 128;
#pragma unroll 2
        for (int c4 = 0; c4 < 16; ++c4) {          // 4 ci per iter
            ull wif0, wco0, wif1, wco1, wif2, wco2, wif3, wco3;
            {
                ulonglong2 w0 = *(const ulonglong2*)(wb + (size_t)(c4 * 4 + 0) * 128);
                ulonglong2 w1 = *(const ulonglong2*)(wb + (size_t)(c4 * 4 + 1) * 128);
                ulonglong2 w2 = *(const ulonglong2*)(wb + (size_t)(c4 * 4 + 2) * 128);
                ulonglong2 w3 = *(const ulonglong2*)(wb + (size_t)(c4 * 4 + 3) * 128);
                wif0 = w0.x; wco0 = w0.y; wif1 = w1.x; wco1 = w1.y;
                wif2 = w2.x; wco2 = w2.y; wif3 = w3.x; wco3 = w3.y;
            }
#pragma unroll
            for (int r = 0; r < 2; ++r)
#pragma unroll
                for (int cx = 0; cx < 8; ++cx) {
                    const float* hp = hb + (r * 10 + cx) * 128 + c4 * 8;
                    ulonglong2 a0 = *(const ulonglong2*)(hp);      // (v0,v0),(v1,v1)
                    ulonglong2 a1 = *(const ulonglong2*)(hp + 4);  // (v2,v2),(v3,v3)
                    const int p = r * 8 + cx;
                    FMA2(acc_if[p], a0.x, wif0); FMA2(acc_co[p], a0.x, wco0);
                    FMA2(acc_if[p], a0.y, wif1); FMA2(acc_co[p], a0.y, wco1);
                    FMA2(acc_if[p], a1.x, wif2); FMA2(acc_co[p], a1.x, wco2);
                    FMA2(acc_if[p], a1.y, wif3); FMA2(acc_co[p], a1.y, wco3);
                }
        }
    }

    // --- input conv: x (ci = 32) ---
    for (int k = 0; k < 9; ++k) {
        const int dy = k / 3, dx = k - dy * 3;
        const ull* __restrict__ wb = g_Wx2 + ((size_t)(k * 32) * 64 + f) * 2;
        const float* __restrict__ xb = shd_x + ((pr0 + dy) * 10 + dx) * 64;
#pragma unroll 2
        for (int c4 = 0; c4 < 8; ++c4) {
            ull wif0, wco0, wif1, wco1, wif2, wco2, wif3, wco3;
            {
                ulonglong2 w0 = *(const ulonglong2*)(wb + (size_t)(c4 * 4 + 0) * 128);
                ulonglong2 w1 = *(const ulonglong2*)(wb + (size_t)(c4 * 4 + 1) * 128);
                ulonglong2 w2 = *(const ulonglong2*)(wb + (size_t)(c4 * 4 + 2) * 128);
                ulonglong2 w3 = *(const ulonglong2*)(wb + (size_t)(c4 * 4 + 3) * 128);
                wif0 = w0.x; wco0 = w0.y; wif1 = w1.x; wco1 = w1.y;
                wif2 = w2.x; wco2 = w2.y; wif3 = w3.x; wco3 = w3.y;
            }
#pragma unroll
            for (int r = 0; r < 2; ++r)
#pragma unroll
                for (int cx = 0; cx < 8; ++cx) {
                    const float* xp = xb + (r * 10 + cx) * 64 + c4 * 8;
                    ulonglong2 a0 = *(const ulonglong2*)(xp);
                    ulonglong2 a1 = *(const ulonglong2*)(xp + 4);
                    const int p = r * 8 + cx;
                    FMA2(acc_if[p], a0.x, wif0); FMA2(acc_co[p], a0.x, wco0);
                    FMA2(acc_if[p], a0.y, wif1); FMA2(acc_co[p], a0.y, wco1);
                    FMA2(acc_if[p], a1.x, wif2); FMA2(acc_co[p], a1.x, wco2);
                    FMA2(acc_if[p], a1.y, wif3); FMA2(acc_co[p], a1.y, wco3);
                }
        }
    }

    // --- gates + state update ---
    float hn[16];
#pragma unroll
    for (int p = 0; p < 16; ++p) {
        int py = ty0 + pr0 + (p >> 3);
        int px = tx0 + (p & 7);
        int cidx = ((bI * 64 + py) * 64 + px) * 64 + f;
        float2 zif = unpack2(acc_if[p]);
        float2 zco = unpack2(acc_co[p]);
        float ig = __saturatef(fmaf(0.2f, zif.x, 0.5f));
        float fg = __saturatef(fmaf(0.2f, zif.y, 0.5f));
        float og = __saturatef(fmaf(0.2f, zco.y, 0.5f));
        float cn = fmaf(fg, g_c[cidx], ig * tanhf(zco.x));
        g_c[cidx] = cn;
        float hv = og * tanhf(cn);
        hout[cidx] = hv;
        hn[p] = hv;
    }

    // --- residual 1x1 projection (x tile already in smem, duplicated layout) ---
    float res[16];
    {
        float bpf = __ldg(bp + f);
#pragma unroll
        for (int p = 0; p < 16; ++p) res[p] = bpf;
    }
#pragma unroll 2
    for (int ci = 0; ci < 32; ++ci) {
        float wv = __ldg(Wp + ci * 64 + f);
#pragma unroll
        for (int r = 0; r < 2; ++r)
#pragma unroll
            for (int cx = 0; cx < 8; ++cx) {
                float xv = shd_x[((pr0 + 1 + r) * 10 + (cx + 1)) * 64 + 2 * ci];
                res[r * 8 + cx] = fmaf(xv, wv, res[r * 8 + cx]);
            }
    }

    // --- write output ---
    float* __restrict__ op = out + (size_t)(bI * TT + t) * 4096 * 64;
#pragma unroll
    for (int p = 0; p < 16; ++p) {
        int py = ty0 + pr0 + (p >> 3);
        int px = tx0 + (p & 7);
        op[(py * 64 + px) * 64 + f] = hn[p] + res[p];
    }
}

// ---------------------------------------------------------------------------
extern "C" void kernel_launch(void* const* d_in, const int* in_sizes, int n_in,
                              void* d_out, int out_size)
{
    const float* x  = (const float*)d_in[0];
    const float* Wx = (const float*)d_in[1];
    const float* Wh = (const float*)d_in[2];
    const float* b  = (const float*)d_in[3];
    const float* Wp = (const float*)d_in[4];
    const float* bp = (const float*)d_in[5];
    float* out = (float*)d_out;

    const int SMEM_BYTES = (100 * 128 + 100 * 64) * 4;   // 76800
    cudaFuncSetAttribute(step_kernel,
                         cudaFuncAttributeMaxDynamicSharedMemorySize, SMEM_BYTES);

    const int nre = 9 * 64 * 64 + 9 * 32 * 64 + 64;
    reorder_kernel<<<(nre + 255) / 256, 256>>>(Wx, Wh, b);

    const int nz = BB * HH * WW * FF;
    zero_kernel<<<(nz + 255) / 256, 256>>>();

    dim3 grid(8, 8, BB);
    for (int t = 0; t < TT; ++t)
        step_kernel<<<grid, 256, SMEM_BYTES>>>(x, Wp, bp, out, t);
}